// round 6
// baseline (speedup 1.0000x reference)
#include <cuda_runtime.h>

// IntShear4: M = S_{P-1} @ ... @ S_0, S_p = I + k_int[p] * e_i e_j^T
// k_int = round-half-even(3*tanh(x)) == sign(x) * (#thresholds below |x|),
//   thresholds: atanh(1/6), atanh(1/2), atanh(5/6)  (3*tanh = 0.5, 1.5, 2.5).
// Left shear == row_i(M) += k * row_j(M): columns evolve independently.
//
// Lane p<P packs (k_int, i*4+j) into one int; one shuffle per step broadcasts.
// Lanes 0..3 own column c of M in registers. Epilogue: butterfly-shuffle
// transpose so lane r holds row r contiguously, stored as one STG.128.

__global__ void intshear4_kernel(const float* __restrict__ k_raw,
                                 const int* __restrict__ pairs_i,
                                 const int* __restrict__ pairs_j,
                                 float* __restrict__ out,
                                 int P) {
    const int lane = threadIdx.x;

    int packed = 0;
    if (lane < P) {
        float x  = k_raw[lane];
        int   ii = pairs_i[lane];
        int   jj = pairs_j[lane];
        float ax = fabsf(x);
        int mag = (ax > 0.16823612f) + (ax > 0.54930614f) + (ax > 1.19894763f);
        int ki  = (x < 0.0f) ? -mag : mag;
        packed  = (ki << 8) | (ii * 4 + jj);
    }

    // Lane c in 0..3 owns column c of M; other lanes compute dead values.
    float m0 = (lane == 0) ? 1.0f : 0.0f;
    float m1 = (lane == 1) ? 1.0f : 0.0f;
    float m2 = (lane == 2) ? 1.0f : 0.0f;
    float m3 = (lane == 3) ? 1.0f : 0.0f;

    if (P == 12) {
#pragma unroll
        for (int p = 0; p < 12; p++) {
            int   w  = __shfl_sync(0xFFFFFFFFu, packed, p);
            float kk = (float)(w >> 8);          // arithmetic shift: signed k_int
            int   jj = w & 3;
            int   ii = (w >> 2) & 3;
            float src = (jj == 0) ? m0 : (jj == 1) ? m1 : (jj == 2) ? m2 : m3;
            float add = kk * src;
            if      (ii == 0) m0 += add;
            else if (ii == 1) m1 += add;
            else if (ii == 2) m2 += add;
            else              m3 += add;
        }
    } else {
        for (int p = 0; p < P; p++) {
            int   w  = __shfl_sync(0xFFFFFFFFu, packed, p);
            float kk = (float)(w >> 8);
            int   jj = w & 3;
            int   ii = (w >> 2) & 3;
            float src = (jj == 0) ? m0 : (jj == 1) ? m1 : (jj == 2) ? m2 : m3;
            float add = kk * src;
            if      (ii == 0) m0 += add;
            else if (ii == 1) m1 += add;
            else if (ii == 2) m2 += add;
            else              m3 += add;
        }
    }

    // Transpose among lanes 0..3: after this, lane r holds row r = M[r][0..3].
    // Butterfly xor1 swaps the off-diagonal 1x1 blocks within lane pairs,
    // butterfly xor2 swaps the off-diagonal 2x2 blocks.
    {
        // Step 1: xor 1. Lanes {0,1}: exchange m-values at the partner's row slot.
        // For column-lane c, rows are m0..m3. Pair partner c^1 differs in bit0.
        float a0 = m0, a1 = m1, a2 = m2, a3 = m3;
        bool hi1 = lane & 1;
        // exchange: element at row (c^1 within 2x2 diag block) swaps across pair
        float t0 = hi1 ? a0 : a1;   // value to send for rows block [0,1]
        float t2 = hi1 ? a2 : a3;   // for rows block [2,3]
        float r0 = __shfl_xor_sync(0xFFFFFFFFu, t0, 1);
        float r2 = __shfl_xor_sync(0xFFFFFFFFu, t2, 1);
        if (hi1) { a0 = r0; a2 = r2; } else { a1 = r0; a3 = r2; }
        // Step 2: xor 2. Exchange the 2-element off-diagonal block.
        bool hi2 = lane & 2;
        float u0 = hi2 ? a0 : a2;
        float u1 = hi2 ? a1 : a3;
        float s0 = __shfl_xor_sync(0xFFFFFFFFu, u0, 2);
        float s1 = __shfl_xor_sync(0xFFFFFFFFu, u1, 2);
        if (hi2) { a0 = s0; a1 = s1; } else { a2 = s0; a3 = s1; }
        // Now lane r (0..3) holds row r: a0..a3 = M[r][0..3].
        if (lane < 4) {
            float4 v = make_float4(a0, a1, a2, a3);
            reinterpret_cast<float4*>(out)[lane] = v;
        }
    }
}

extern "C" void kernel_launch(void* const* d_in, const int* in_sizes, int n_in,
                              void* d_out, int out_size) {
    const float* k_raw   = (const float*)d_in[0];
    const int*   pairs_i = (const int*)d_in[1];
    const int*   pairs_j = (const int*)d_in[2];
    float* out = (float*)d_out;
    int P = in_sizes[0];
    intshear4_kernel<<<1, 32>>>(k_raw, pairs_i, pairs_j, out, P);
}

// round 7
// speedup vs baseline: 1.0207x; 1.0207x over previous
#include <cuda_runtime.h>

// IntShear4: M = S_{P-1} @ ... @ S_0, S_p = I + k_int[p] * e_i e_j^T
// k_int = round-half-even(3*tanh(x)) == sign(x) * (#thresholds below |x|),
//   thresholds: atanh(1/6), atanh(1/2), atanh(5/6)  (3*tanh = 0.5, 1.5, 2.5).
// Left shear == row_i(M) += k * row_j(M): columns of M evolve independently.
//
// Lane p<P loads its triple and packs (k_int, i*4+j) into ONE int:
//   packed = (k_int << 8) | (i*4 + j)   (arithmetic shift recovers signed k)
// One shuffle per step broadcasts it; lanes 0..3 each own one column of M in
// registers and store their column at the end.

__global__ void intshear4_kernel(const float* __restrict__ k_raw,
                                 const int* __restrict__ pairs_i,
                                 const int* __restrict__ pairs_j,
                                 float* __restrict__ out,
                                 int P) {
    const int lane = threadIdx.x;

    int packed = 0;
    if (lane < P) {
        float x  = k_raw[lane];
        int   ii = pairs_i[lane];
        int   jj = pairs_j[lane];
        float ax = fabsf(x);
        int mag = (ax > 0.16823612f) + (ax > 0.54930614f) + (ax > 1.19894763f);
        int ki  = (x < 0.0f) ? -mag : mag;
        packed  = (ki << 8) | (ii * 4 + jj);
    }

    // Lane c in 0..3 owns column c of M; other lanes compute dead values.
    float m0 = (lane == 0) ? 1.0f : 0.0f;
    float m1 = (lane == 1) ? 1.0f : 0.0f;
    float m2 = (lane == 2) ? 1.0f : 0.0f;
    float m3 = (lane == 3) ? 1.0f : 0.0f;

    if (P == 12) {
#pragma unroll
        for (int p = 0; p < 12; p++) {
            int   w  = __shfl_sync(0xFFFFFFFFu, packed, p);
            float kk = (float)(w >> 8);          // arithmetic shift: signed k_int
            int   jj = w & 3;
            int   ii = (w >> 2) & 3;
            float src = (jj == 0) ? m0 : (jj == 1) ? m1 : (jj == 2) ? m2 : m3;
            float add = kk * src;
            if      (ii == 0) m0 += add;
            else if (ii == 1) m1 += add;
            else if (ii == 2) m2 += add;
            else              m3 += add;
        }
    } else {
        for (int p = 0; p < P; p++) {
            int   w  = __shfl_sync(0xFFFFFFFFu, packed, p);
            float kk = (float)(w >> 8);
            int   jj = w & 3;
            int   ii = (w >> 2) & 3;
            float src = (jj == 0) ? m0 : (jj == 1) ? m1 : (jj == 2) ? m2 : m3;
            float add = kk * src;
            if      (ii == 0) m0 += add;
            else if (ii == 1) m1 += add;
            else if (ii == 2) m2 += add;
            else              m3 += add;
        }
    }

    if (lane < 4) {
        // out is row-major [4,4]; lane = column index
        out[0 * 4 + lane] = m0;
        out[1 * 4 + lane] = m1;
        out[2 * 4 + lane] = m2;
        out[3 * 4 + lane] = m3;
    }
}

extern "C" void kernel_launch(void* const* d_in, const int* in_sizes, int n_in,
                              void* d_out, int out_size) {
    const float* k_raw   = (const float*)d_in[0];
    const int*   pairs_i = (const int*)d_in[1];
    const int*   pairs_j = (const int*)d_in[2];
    float* out = (float*)d_out;
    int P = in_sizes[0];
    intshear4_kernel<<<1, 32>>>(k_raw, pairs_i, pairs_j, out, P);
}